// round 1
// baseline (speedup 1.0000x reference)
#include <cuda_runtime.h>
#include <cuda_bf16.h>
#include <cstdint>
#include <math.h>

#define NB 128
#define NT 8
#define ND 2048
#define NR 4
#define NV 512
#define NN 8192   // V*R*R

// ---------------- scratch (no allocation allowed) ----------------
__device__ __nv_bfloat16 g_xbar[NB * ND];   // mean over T, bf16   (512 KB)
__device__ float g_alpha[NB * NR];
__device__ float g_beta[NB * NR];
__device__ float g_core[NB * NN];           // |xbar @ w_vocab|    (4 MB)
__device__ float g_loss[NB];

// =================================================================
// Kernel A: xbar = mean_t(input_embs), alpha/beta = |xbar @ w_{a,b}|
// one block per batch, 256 threads
// =================================================================
__global__ __launch_bounds__(256) void prep_kernel(
    const float* __restrict__ x, const float* __restrict__ wa,
    const float* __restrict__ wb) {
  const int b = blockIdx.x;
  const int tid = threadIdx.x;
  const int lane = tid & 31;
  const int warp = tid >> 5;
  const float* xb = x + (size_t)b * NT * ND;

  float p[8] = {0.f, 0.f, 0.f, 0.f, 0.f, 0.f, 0.f, 0.f};
  for (int d = tid; d < ND; d += 256) {
    float s = 0.f;
#pragma unroll
    for (int t = 0; t < NT; t++) s += xb[t * ND + d];
    s *= 0.125f;
    g_xbar[b * ND + d] = __float2bfloat16(s);
    float4 a4 = *reinterpret_cast<const float4*>(wa + d * 4);
    float4 b4 = *reinterpret_cast<const float4*>(wb + d * 4);
    p[0] += s * a4.x; p[1] += s * a4.y; p[2] += s * a4.z; p[3] += s * a4.w;
    p[4] += s * b4.x; p[5] += s * b4.y; p[6] += s * b4.z; p[7] += s * b4.w;
  }

  __shared__ float sred[8][8];
#pragma unroll
  for (int q = 0; q < 8; q++) {
    float v = p[q];
#pragma unroll
    for (int o = 16; o; o >>= 1) v += __shfl_xor_sync(0xFFFFFFFFu, v, o);
    if (lane == 0) sred[warp][q] = v;
  }
  __syncthreads();
  if (tid < 8) {
    float s = 0.f;
#pragma unroll
    for (int w = 0; w < 8; w++) s += sred[w][tid];
    s = fabsf(s);
    if (tid < 4) g_alpha[b * 4 + tid] = s;
    else         g_beta[b * 4 + (tid - 4)] = s;
  }
}

// =================================================================
// Kernel B: core = |xbar[128,2048] @ w_vocab[2048,8192]|  (bf16 MMA)
// 128 blocks (BN=64 each), 256 threads (8 warps: 4 in M x 2 in N)
// BM=128, BN=64, BK=64, double-buffered smem, XOR-swizzled rows
// =================================================================
__device__ __forceinline__ void ldsm_x4(unsigned& r0, unsigned& r1,
                                        unsigned& r2, unsigned& r3,
                                        unsigned addr) {
  asm volatile("ldmatrix.sync.aligned.m8n8.x4.shared.b16 {%0,%1,%2,%3}, [%4];"
               : "=r"(r0), "=r"(r1), "=r"(r2), "=r"(r3) : "r"(addr));
}
__device__ __forceinline__ void ldsm_x4_t(unsigned& r0, unsigned& r1,
                                          unsigned& r2, unsigned& r3,
                                          unsigned addr) {
  asm volatile("ldmatrix.sync.aligned.m8n8.x4.trans.shared.b16 {%0,%1,%2,%3}, [%4];"
               : "=r"(r0), "=r"(r1), "=r"(r2), "=r"(r3) : "r"(addr));
}
__device__ __forceinline__ void mma16816(float& c0, float& c1, float& c2, float& c3,
                                         unsigned a0, unsigned a1, unsigned a2,
                                         unsigned a3, unsigned b0, unsigned b1) {
  asm volatile(
      "mma.sync.aligned.m16n8k16.row.col.f32.bf16.bf16.f32 "
      "{%0,%1,%2,%3}, {%4,%5,%6,%7}, {%8,%9}, {%0,%1,%2,%3};"
      : "+f"(c0), "+f"(c1), "+f"(c2), "+f"(c3)
      : "r"(a0), "r"(a1), "r"(a2), "r"(a3), "r"(b0), "r"(b1));
}

__global__ __launch_bounds__(256, 1) void gemm_kernel(const float* __restrict__ wv) {
  __shared__ __align__(16) __nv_bfloat16 Ash[2][128 * 64];  // 32 KB
  __shared__ __align__(16) __nv_bfloat16 Bsh[2][64 * 64];   // 16 KB

  const int tid = threadIdx.x;
  const int lane = tid & 31;
  const int warp = tid >> 5;
  const int wm = warp & 3;   // M group: rows 32*wm..
  const int wn = warp >> 2;  // N group: cols 32*wn..
  const int n0 = blockIdx.x * 64;

  float c[2][4][4];
#pragma unroll
  for (int mi = 0; mi < 2; mi++)
#pragma unroll
    for (int ni = 0; ni < 4; ni++)
#pragma unroll
      for (int q = 0; q < 4; q++) c[mi][ni][q] = 0.f;

  const unsigned aBase = (unsigned)__cvta_generic_to_shared(&Ash[0][0]);
  const unsigned bBase = (unsigned)__cvta_generic_to_shared(&Bsh[0][0]);
  const int lm = lane & 15;
  const int lh = lane >> 4;  // 0/1

  uint4 ar[4];
  float4 br[4];

  auto ldg = [&](int it) {
    const int k0 = it * 64;
#pragma unroll
    for (int i = 0; i < 4; i++) {
      int idx = tid + 256 * i;
      int row = idx >> 3, ch = idx & 7;       // A: 128 rows x 8 chunks of 16B
      ar[i] = *reinterpret_cast<const uint4*>(&g_xbar[row * ND + k0 + ch * 8]);
    }
#pragma unroll
    for (int i = 0; i < 4; i++) {
      int idx = tid + 256 * i;
      int row = idx >> 4, f4 = idx & 15;      // B: 64 rows x 16 float4
      br[i] = *reinterpret_cast<const float4*>(wv + (k0 + row) * NN + n0 + f4 * 4);
    }
  };
  auto sts = [&](int buf) {
#pragma unroll
    for (int i = 0; i < 4; i++) {
      int idx = tid + 256 * i;
      int row = idx >> 3, ch = idx & 7;
      int s = row * 64 + ((ch ^ (row & 7)) << 3);      // XOR swizzle, bf16 units
      *reinterpret_cast<uint4*>(&Ash[buf][s]) = ar[i];
    }
#pragma unroll
    for (int i = 0; i < 4; i++) {
      int idx = tid + 256 * i;
      int row = idx >> 4, f4 = idx & 15;
      __nv_bfloat162 lo = __floats2bfloat162_rn(br[i].x, br[i].y);
      __nv_bfloat162 hi = __floats2bfloat162_rn(br[i].z, br[i].w);
      int s = row * 64 + (((f4 >> 1) ^ (row & 7)) << 3) + (f4 & 1) * 4;
      unsigned* p = reinterpret_cast<unsigned*>(&Bsh[buf][s]);
      p[0] = *reinterpret_cast<unsigned*>(&lo);
      p[1] = *reinterpret_cast<unsigned*>(&hi);
    }
  };
  auto compute = [&](int buf) {
    const unsigned aB = aBase + buf * (128 * 64 * 2);
    const unsigned bB = bBase + buf * (64 * 64 * 2);
#pragma unroll
    for (int ks = 0; ks < 4; ks++) {
      unsigned a[2][4], bf[4][2];
#pragma unroll
      for (int mi = 0; mi < 2; mi++) {
        int mrow = wm * 32 + mi * 16 + lm;
        int kc = ks * 2 + lh;                            // 16B chunk of k
        int s = mrow * 64 + ((kc ^ (mrow & 7)) << 3);
        ldsm_x4(a[mi][0], a[mi][1], a[mi][2], a[mi][3], aB + s * 2);
      }
#pragma unroll
      for (int ni2 = 0; ni2 < 2; ni2++) {
        int kr = ks * 16 + lm;
        int nch = wn * 4 + ni2 * 2 + lh;                 // 16B chunk of n
        int s = kr * 64 + ((nch ^ (kr & 7)) << 3);
        unsigned r0, r1, r2, r3;
        ldsm_x4_t(r0, r1, r2, r3, bB + s * 2);
        bf[ni2 * 2 + 0][0] = r0; bf[ni2 * 2 + 0][1] = r1;
        bf[ni2 * 2 + 1][0] = r2; bf[ni2 * 2 + 1][1] = r3;
      }
#pragma unroll
      for (int mi = 0; mi < 2; mi++)
#pragma unroll
        for (int ni = 0; ni < 4; ni++)
          mma16816(c[mi][ni][0], c[mi][ni][1], c[mi][ni][2], c[mi][ni][3],
                   a[mi][0], a[mi][1], a[mi][2], a[mi][3],
                   bf[ni][0], bf[ni][1]);
    }
  };

  ldg(0);
  sts(0);
  __syncthreads();
#pragma unroll 1
  for (int it = 0; it < 32; it++) {
    const int buf = it & 1;
    if (it < 31) ldg(it + 1);
    compute(buf);
    if (it < 31) {
      sts(buf ^ 1);
      __syncthreads();
    }
  }

  // epilogue: |.| and store fp32 core
#pragma unroll
  for (int mi = 0; mi < 2; mi++) {
#pragma unroll
    for (int ni = 0; ni < 4; ni++) {
      int m = wm * 32 + mi * 16 + (lane >> 2);
      int n = n0 + wn * 32 + ni * 8 + (lane & 3) * 2;
      float2 v0 = make_float2(fabsf(c[mi][ni][0]), fabsf(c[mi][ni][1]));
      float2 v1 = make_float2(fabsf(c[mi][ni][2]), fabsf(c[mi][ni][3]));
      *reinterpret_cast<float2*>(&g_core[m * NN + n]) = v0;
      *reinterpret_cast<float2*>(&g_core[(m + 8) * NN + n]) = v1;
    }
  }
}

// =================================================================
// Kernel C: per-batch marg sum, label gather, 4x4 chain, loss_b
// one block per batch, 128 threads
// =================================================================
__global__ __launch_bounds__(128) void finalize_kernel(const int* __restrict__ labels) {
  const int b = blockIdx.x;
  const int tid = threadIdx.x;
  const float* cb = g_core + (size_t)b * NN;

  __shared__ float part[8][16];
  __shared__ float marg[16];

  const int ij = tid & 15, vs = tid >> 4;
  const int i = ij >> 2, j = ij & 3;
  float s = 0.f;
  for (int v = vs * 64; v < vs * 64 + 64; v++)
    s += cb[i * (NV * NR) + v * NR + j];
  part[vs][ij] = s;
  __syncthreads();
  if (tid < 16) {
    float m = 0.f;
#pragma unroll
    for (int w = 0; w < 8; w++) m += part[w][tid];
    marg[tid] = m;
  }
  __syncthreads();

  if (tid == 0) {
    float res[16], tmp[16], mt[16];
    int lab = labels[b * NT];
#pragma unroll
    for (int q = 0; q < 16; q++)
      res[q] = cb[(q >> 2) * (NV * NR) + lab * NR + (q & 3)];
    for (int t = 1; t < NT; t++) {
      lab = labels[b * NT + t];
#pragma unroll
      for (int q = 0; q < 16; q++)
        mt[q] = cb[(q >> 2) * (NV * NR) + lab * NR + (q & 3)];
#pragma unroll
      for (int ii = 0; ii < 4; ii++)
#pragma unroll
        for (int jj = 0; jj < 4; jj++) {
          float acc = 0.f;
#pragma unroll
          for (int kk = 0; kk < 4; kk++) acc += res[ii * 4 + kk] * mt[kk * 4 + jj];
          tmp[ii * 4 + jj] = acc;
        }
#pragma unroll
      for (int q = 0; q < 16; q++) res[q] = tmp[q];
    }
    const float* al = g_alpha + b * 4;
    const float* be = g_beta + b * 4;
    float u = 0.f;
#pragma unroll
    for (int ii = 0; ii < 4; ii++)
#pragma unroll
      for (int jj = 0; jj < 4; jj++) u += al[ii] * res[ii * 4 + jj] * be[jj];

    float zc[16];
#pragma unroll
    for (int q = 0; q < 16; q++) zc[q] = marg[q];
    for (int t = 0; t < NT; t++) {   // zc = marg^(T+1)
#pragma unroll
      for (int ii = 0; ii < 4; ii++)
#pragma unroll
        for (int jj = 0; jj < 4; jj++) {
          float acc = 0.f;
#pragma unroll
          for (int kk = 0; kk < 4; kk++) acc += zc[ii * 4 + kk] * marg[kk * 4 + jj];
          tmp[ii * 4 + jj] = acc;
        }
#pragma unroll
      for (int q = 0; q < 16; q++) zc[q] = tmp[q];
    }
    float z = 0.f;
#pragma unroll
    for (int ii = 0; ii < 4; ii++)
#pragma unroll
      for (int jj = 0; jj < 4; jj++) z += al[ii] * zc[ii * 4 + jj] * be[jj];

    g_loss[b] = logf(z) - logf(u);   // = -log(u/z)
  }
}

// =================================================================
// Kernel D: mean over batches -> d_out[0]
// =================================================================
__global__ __launch_bounds__(128) void reduce_kernel(float* __restrict__ out) {
  const int tid = threadIdx.x;
  float v = g_loss[tid];
#pragma unroll
  for (int o = 16; o; o >>= 1) v += __shfl_xor_sync(0xFFFFFFFFu, v, o);
  __shared__ float sw[4];
  if ((tid & 31) == 0) sw[tid >> 5] = v;
  __syncthreads();
  if (tid == 0) out[0] = (sw[0] + sw[1] + sw[2] + sw[3]) * (1.0f / 128.0f);
}

// =================================================================
extern "C" void kernel_launch(void* const* d_in, const int* in_sizes, int n_in,
                              void* d_out, int out_size) {
  const float* x      = (const float*)d_in[0];   // [128, 8, 2048]
  const int*   labels = (const int*)  d_in[1];   // [128, 8]
  const float* wa     = (const float*)d_in[2];   // [2048, 4]
  const float* wb     = (const float*)d_in[3];   // [2048, 4]
  const float* wv     = (const float*)d_in[4];   // [2048, 8192]
  float* out = (float*)d_out;

  prep_kernel<<<NB, 256>>>(x, wa, wb);
  gemm_kernel<<<NN / 64, 256>>>(wv);
  finalize_kernel<<<NB, 128>>>(labels);
  reduce_kernel<<<1, 128>>>(out);
}